// round 7
// baseline (speedup 1.0000x reference)
#include <cuda_runtime.h>
#include <cuda_bf16.h>
#include <cstdint>

#define T_ITER 8
#define L_DIM  4096
#define D_DIM  512
#define H_DIM  256
#define M_TOT  (T_ITER * L_DIM)

// ---------------- scratch ----------------
__device__ __nv_bfloat16  g_BT[H_DIM * D_DIM];          // Ws^T bf16, [n][k]

__device__ __forceinline__ float tanhap(float x) {
    float y; asm("tanh.approx.f32 %0, %1;" : "=f"(y) : "f"(x)); return y;
}

// ---------------- kernel 0: Ws (512x256 [k][n]) -> g_BT ([n][k]) bf16 ----------------
__global__ void k_convert_ws(const float* __restrict__ Ws) {
    __shared__ float tile[32][33];
    int bx = blockIdx.x, by = blockIdx.y;
    int tx = threadIdx.x, ty = threadIdx.y;   // 32 x 8
    #pragma unroll
    for (int i = 0; i < 4; i++) {
        int k = by * 32 + ty + i * 8;
        tile[ty + i * 8][tx] = Ws[k * H_DIM + bx * 32 + tx];
    }
    __syncthreads();
    #pragma unroll
    for (int i = 0; i < 4; i++) {
        int n = bx * 32 + ty + i * 8;
        g_BT[n * D_DIM + by * 32 + tx] = __float2bfloat16(tile[tx][ty + i * 8]);
    }
}

// ---------------- fused kernel: GEMM + dots + full recurrence, one CTA = 16 l x 8 t --
#define BM 128
#define BK 32
#define SAS 40                                   // staging row stride (bf16), conflict-free
#define SZ_A (BM * SAS * 2)                      // 10240 B / stage
#define SZ_B (H_DIM * SAS * 2)                   // 20480 B / stage
#define OFF_A0 0
#define OFF_A1 (SZ_A)
#define OFF_B0 (2 * SZ_A)
#define OFF_B1 (2 * SZ_A + SZ_B)
// E buffer overlaps staging (used strictly after mainloop, one barrier between)
#define ESTR   260                               // fp32 stride: conflict-free scalar reads
#define SZ_E   (BM * ESTR * 4)                   // 133120 B
#define OFF_DX (SZ_E)                            // sdxyz: 128 rows x 3 fp32
#define SMEM_TOTAL (OFF_DX + BM * 3 * 4)

__device__ __forceinline__ void mma_bf16(float c[4],
                                         uint32_t a0, uint32_t a1, uint32_t a2, uint32_t a3,
                                         uint32_t b0, uint32_t b1) {
    asm volatile(
        "mma.sync.aligned.m16n8k16.row.col.f32.bf16.bf16.f32 "
        "{%0,%1,%2,%3}, {%4,%5,%6,%7}, {%8,%9}, {%0,%1,%2,%3};\n"
        : "+f"(c[0]), "+f"(c[1]), "+f"(c[2]), "+f"(c[3])
        : "r"(a0), "r"(a1), "r"(a2), "r"(a3), "r"(b0), "r"(b1));
}
__device__ __forceinline__ void ldsm_x4(uint32_t addr, uint32_t& r0, uint32_t& r1,
                                        uint32_t& r2, uint32_t& r3) {
    asm volatile("ldmatrix.sync.aligned.m8n8.x4.shared.b16 {%0,%1,%2,%3}, [%4];"
                 : "=r"(r0), "=r"(r1), "=r"(r2), "=r"(r3) : "r"(addr));
}
__device__ __forceinline__ void cp16(uint32_t dst, const void* src) {
    asm volatile("cp.async.ca.shared.global [%0], [%1], 16;" :: "r"(dst), "l"(src) : "memory");
}

__global__ void __launch_bounds__(512, 1) k_fused(const float* __restrict__ A,
                                                  const float* __restrict__ Wx,
                                                  const float* __restrict__ Wy,
                                                  const float* __restrict__ Wz,
                                                  const float* __restrict__ Wh,
                                                  const float* __restrict__ bs,
                                                  const float* __restrict__ rois,
                                                  const float* __restrict__ bxg,
                                                  const float* __restrict__ byg,
                                                  const float* __restrict__ bzg,
                                                  float* __restrict__ out) {
    extern __shared__ __align__(128) char smem[];
    uint32_t sbase;
    asm("{ .reg .u64 t; cvta.to.shared.u64 t, %1; cvt.u32.u64 %0, t; }" : "=r"(sbase) : "l"(smem));

    const int tid  = threadIdx.x;
    const int lane = tid & 31, wid = tid >> 5;
    const int grp  = lane >> 2, tig = lane & 3;
    const int lbase = blockIdx.x * 16;            // 16 l's per CTA, all 8 t's

    // staging: thread owns one (t,l) row, 8 cols per kt
    const int mrow = tid >> 2;                    // local row 0..127 = t*16 + (l-lbase)
    const int t_st = mrow >> 4;
    const int l_st = lbase + (mrow & 15);
    const float* Arow = A  + ((size_t)t_st * L_DIM + l_st) * D_DIM + (tid & 3) * 8;
    const float* wxp  = Wx + (size_t)l_st * D_DIM + (tid & 3) * 8;
    const float* wyp  = Wy + (size_t)l_st * D_DIM + (tid & 3) * 8;
    const float* wzp  = Wz + (size_t)l_st * D_DIM + (tid & 3) * 8;
    const uint32_t aDst = (uint32_t)(mrow * SAS + (tid & 3) * 8) * 2;
    // B staging
    const int bn = tid >> 1;
    const int bsg = (tid & 1) * 2;
    const __nv_bfloat16* Bsrc = g_BT + (size_t)bn * D_DIM + bsg * 8;
    const uint32_t bDst = (uint32_t)(bn * SAS + bsg * 8) * 2;

    // ldmatrix lane addressing
    const int aRowL = lane & 15;
    const int aColL = (lane >> 4) << 3;
    const int bRowL = (lane & 7) + ((lane >> 4) << 3);
    const int bColL = ((lane >> 3) & 1) << 3;
    const uint32_t offA[2] = {sbase + OFF_A0, sbase + OFF_A1};
    const uint32_t offB[2] = {sbase + OFF_B0, sbase + OFF_B1};

    // warp tile: 4 M-warps x 4 N-warps (32 x 64 each)
    const int wm = (wid & 3) * 32;
    const int wn = (wid >> 2) * 64;

    float acc[2][8][4];
    #pragma unroll
    for (int i = 0; i < 2; i++)
        #pragma unroll
        for (int j = 0; j < 8; j++)
            #pragma unroll
            for (int r = 0; r < 4; r++) acc[i][j][r] = 0.f;

    float dx = 0.f, dy = 0.f, dz = 0.f;
    float4 ar0 = *(const float4*)(Arow);
    float4 ar1 = *(const float4*)(Arow + 4);

    for (int kt = 0; kt < D_DIM / BK; kt++) {
        const int s = kt & 1;
        // ---- stage A (cvt + pack) ----
        {
            __nv_bfloat162 b01 = __float22bfloat162_rn(make_float2(ar0.x, ar0.y));
            __nv_bfloat162 b23 = __float22bfloat162_rn(make_float2(ar0.z, ar0.w));
            __nv_bfloat162 b45 = __float22bfloat162_rn(make_float2(ar1.x, ar1.y));
            __nv_bfloat162 b67 = __float22bfloat162_rn(make_float2(ar1.z, ar1.w));
            uint4 v = make_uint4(*(uint32_t*)&b01, *(uint32_t*)&b23,
                                 *(uint32_t*)&b45, *(uint32_t*)&b67);
            asm volatile("st.shared.v4.b32 [%0], {%1,%2,%3,%4};"
                         :: "r"(offA[s] + aDst), "r"(v.x), "r"(v.y), "r"(v.z), "r"(v.w) : "memory");
        }
        // ---- dec dots on current A regs ----
        {
            const float4 x0 = *(const float4*)(wxp + kt * BK);
            const float4 x1 = *(const float4*)(wxp + kt * BK + 4);
            const float4 y0 = *(const float4*)(wyp + kt * BK);
            const float4 y1 = *(const float4*)(wyp + kt * BK + 4);
            const float4 z0 = *(const float4*)(wzp + kt * BK);
            const float4 z1 = *(const float4*)(wzp + kt * BK + 4);
            dx += ar0.x*x0.x + ar0.y*x0.y + ar0.z*x0.z + ar0.w*x0.w
                + ar1.x*x1.x + ar1.y*x1.y + ar1.z*x1.z + ar1.w*x1.w;
            dy += ar0.x*y0.x + ar0.y*y0.y + ar0.z*y0.z + ar0.w*y0.w
                + ar1.x*y1.x + ar1.y*y1.y + ar1.z*y1.z + ar1.w*y1.w;
            dz += ar0.x*z0.x + ar0.y*z0.y + ar0.z*z0.z + ar0.w*z0.w
                + ar1.x*z1.x + ar1.y*z1.y + ar1.z*z1.z + ar1.w*z1.w;
        }
        // ---- stage B via cp.async ----
        cp16(offB[s] + bDst,      Bsrc + kt * BK);
        cp16(offB[s] + bDst + 16, Bsrc + kt * BK + 8);
        asm volatile("cp.async.commit_group;" ::: "memory");
        // ---- prefetch next A ----
        if (kt + 1 < D_DIM / BK) {
            ar0 = *(const float4*)(Arow + (kt + 1) * BK);
            ar1 = *(const float4*)(Arow + (kt + 1) * BK + 4);
        }
        asm volatile("cp.async.wait_group 0;" ::: "memory");
        __syncthreads();

        // ---- compute ----
        #pragma unroll
        for (int ks = 0; ks < 2; ks++) {
            uint32_t bf[8][2];
            #pragma unroll
            for (int p = 0; p < 4; p++) {
                uint32_t addr = offB[s] + 2u * ((wn + p * 16 + bRowL) * SAS + ks * 16 + bColL);
                ldsm_x4(addr, bf[2*p][0], bf[2*p][1], bf[2*p+1][0], bf[2*p+1][1]);
            }
            #pragma unroll
            for (int mi = 0; mi < 2; mi++) {
                uint32_t a0, a1, a2, a3;
                uint32_t addr = offA[s] + 2u * ((wm + mi * 16 + aRowL) * SAS + ks * 16 + aColL);
                ldsm_x4(addr, a0, a1, a2, a3);
                #pragma unroll
                for (int ni = 0; ni < 8; ni++)
                    mma_bf16(acc[mi][ni], a0, a1, a2, a3, bf[ni][0], bf[ni][1]);
            }
        }
    }

    // mainloop staging regions are dead after this barrier; reuse as E buffer
    __syncthreads();

    float* sE  = (float*)smem;                    // [128][ESTR]
    float* sdx = (float*)(smem + OFF_DX);         // [128][3]

    // ---- dots -> smem (quad reduce) ----
    dx += __shfl_xor_sync(0xffffffffu, dx, 1); dx += __shfl_xor_sync(0xffffffffu, dx, 2);
    dy += __shfl_xor_sync(0xffffffffu, dy, 1); dy += __shfl_xor_sync(0xffffffffu, dy, 2);
    dz += __shfl_xor_sync(0xffffffffu, dz, 1); dz += __shfl_xor_sync(0xffffffffu, dz, 2);
    if ((tid & 3) == 0) {
        sdx[mrow * 3 + 0] = dx;
        sdx[mrow * 3 + 1] = dy;
        sdx[mrow * 3 + 2] = dz;
    }

    // ---- accumulators -> smem E ----
    #pragma unroll
    for (int mi = 0; mi < 2; mi++) {
        int r0 = wm + mi * 16 + grp;
        int r1 = r0 + 8;
        #pragma unroll
        for (int ni = 0; ni < 8; ni++) {
            int col = wn + ni * 8 + 2 * tig;
            *(float2*)&sE[r0 * ESTR + col] = make_float2(acc[mi][ni][0], acc[mi][ni][1]);
            *(float2*)&sE[r1 * ESTR + col] = make_float2(acc[mi][ni][2], acc[mi][ni][3]);
        }
    }
    __syncthreads();

    // ---- in-CTA sequential recurrence: warp wid <-> l = lbase + wid ----
    {
        const int wl = wid;                       // 0..15
        const int l  = lbase + wl;
        float wh[8], bsr[8], S[8];
        #pragma unroll
        for (int i = 0; i < 8; i++) {
            int j = i * 32 + lane;
            wh[i]  = Wh[(size_t)l * H_DIM + j];
            bsr[i] = bs[j];
            S[i]   = sE[wl * ESTR + j];           // t=0 row
        }
        float X = sdx[wl * 3 + 0];
        float Y = sdx[wl * 3 + 1];
        float Z = sdx[wl * 3 + 2];
        float cx = rois[(size_t)l * 3 + 0];
        float cy = rois[(size_t)l * 3 + 1];
        float cz = rois[(size_t)l * 3 + 2];
        float bxl = bxg[l], byl = byg[l], bzl = bzg[l];
        const float s0 = 1.0f / 767.0f, s2 = 1.0f / 575.0f;

        float px = (X + bxl) * s0 + cx;
        float py = (Y + byl) * s0 + cy;
        float pz = (Z + bzl) * s2 + cz;
        if (lane == 0) {
            out[(size_t)l * 3 + 0] = px;
            out[(size_t)l * 3 + 1] = py;
            out[(size_t)l * 3 + 2] = pz;
        }

        #pragma unroll
        for (int t = 1; t < T_ITER; t++) {
            const int r = t * 16 + wl;
            float e[8], qf[8], qa[8];
            #pragma unroll
            for (int i = 0; i < 8; i++) {
                e[i]  = sE[r * ESTR + i * 32 + lane];
                qf[i] = wh[i] * tanhap(S[i] + bsr[i]);
                qa[i] = wh[i] * tanhap(e[i] + bsr[i]);
            }
            float pf = ((qf[0]+qf[1]) + (qf[2]+qf[3])) + ((qf[4]+qf[5]) + (qf[6]+qf[7]));
            float pa = ((qa[0]+qa[1]) + (qa[2]+qa[3])) + ((qa[4]+qa[5]) + (qa[6]+qa[7]));
            #pragma unroll
            for (int o = 16; o > 0; o >>= 1) {
                pf += __shfl_xor_sync(0xffffffffu, pf, o);
                pa += __shfl_xor_sync(0xffffffffu, pa, o);
            }
            // g0 = sigmoid(pf - pa); bh cancels in the 2-way softmax
            float g0 = fmaf(0.5f, tanhap(0.5f * (pf - pa)), 0.5f);
            float g1 = 1.0f - g0;

            #pragma unroll
            for (int i = 0; i < 8; i++) S[i] = g0 * S[i] + g1 * e[i];

            X = g0 * X + g1 * sdx[r * 3 + 0];
            Y = g0 * Y + g1 * sdx[r * 3 + 1];
            Z = g0 * Z + g1 * sdx[r * 3 + 2];
            cx = g0 * cx + g1 * px;
            cy = g0 * cy + g1 * py;
            cz = g0 * cz + g1 * pz;
            px = (X + bxl) * s0 + cx;
            py = (Y + byl) * s0 + cy;
            pz = (Z + bzl) * s2 + cz;
            if (lane == 0) {
                size_t ro = (size_t)t * L_DIM + l;
                out[ro * 3 + 0] = px;
                out[ro * 3 + 1] = py;
                out[ro * 3 + 2] = pz;
            }
        }
    }
}

// ---------------- launch ----------------
extern "C" void kernel_launch(void* const* d_in, const int* in_sizes, int n_in,
                              void* d_out, int out_size) {
    const float* emb  = (const float*)d_in[0];
    const float* rois = (const float*)d_in[1];
    const float* Wx   = (const float*)d_in[2];
    const float* bx   = (const float*)d_in[3];
    const float* Wy   = (const float*)d_in[4];
    const float* by   = (const float*)d_in[5];
    const float* Wz   = (const float*)d_in[6];
    const float* bz   = (const float*)d_in[7];
    const float* Ws   = (const float*)d_in[8];
    const float* bs   = (const float*)d_in[9];
    const float* Wh   = (const float*)d_in[10];
    // d_in[11] = bh: cancels in the 2-way softmax.
    float* out = (float*)d_out;

    static int attr_set = 0;
    if (!attr_set) {
        cudaFuncSetAttribute(k_fused, cudaFuncAttributeMaxDynamicSharedMemorySize, SMEM_TOTAL);
        attr_set = 1;
    }

    k_convert_ws<<<dim3(8, 16), dim3(32, 8)>>>(Ws);
    k_fused<<<L_DIM / 16, 512, SMEM_TOTAL>>>(emb, Wx, Wy, Wz, Wh, bs,
                                             rois, bx, by, bz, out);
}

// round 8
// speedup vs baseline: 1.2183x; 1.2183x over previous
#include <cuda_runtime.h>
#include <cuda_fp16.h>
#include <cstdint>

#define T_ITER 8
#define L_DIM  4096
#define D_DIM  512
#define H_DIM  256
#define M_TOT  (T_ITER * L_DIM)

// ---------------- scratch ----------------
__device__ float   g_E[(size_t)M_TOT * H_DIM];
__device__ float   g_dxyz[(size_t)M_TOT * 3];
__device__ float   g_pa[M_TOT];
__device__ __half  g_BT[H_DIM * D_DIM];                 // Ws^T f16, [n][k]

__device__ __forceinline__ float tanhap(float x) {
    float y; asm("tanh.approx.f32 %0, %1;" : "=f"(y) : "f"(x)); return y;
}

// ---------------- kernel 0: Ws (512x256 [k][n]) -> g_BT ([n][k]) f16 ----------------
__global__ void k_convert_ws(const float* __restrict__ Ws) {
    __shared__ float tile[32][33];
    int bx = blockIdx.x, by = blockIdx.y;
    int tx = threadIdx.x, ty = threadIdx.y;   // 32 x 8
    #pragma unroll
    for (int i = 0; i < 4; i++) {
        int k = by * 32 + ty + i * 8;
        tile[ty + i * 8][tx] = Ws[k * H_DIM + bx * 32 + tx];
    }
    __syncthreads();
    #pragma unroll
    for (int i = 0; i < 4; i++) {
        int n = bx * 32 + ty + i * 8;
        g_BT[n * D_DIM + by * 32 + tx] = __float2half(tile[tx][ty + i * 8]);
    }
}

// ---------------- kernel 1: GEMM f16 (one CTA = 16 l x 8 t rows, full N=256) --------
#define BM 128
#define BK 32
#define SAS 40
#define SZ_A (BM * SAS * 2)
#define SZ_B (H_DIM * SAS * 2)
#define OFF_A0 0
#define OFF_A1 (SZ_A)
#define OFF_B0 (2 * SZ_A)
#define OFF_B1 (2 * SZ_A + SZ_B)
#define OFF_SPA (2 * SZ_A + 2 * SZ_B)
#define SMEM_TOTAL (OFF_SPA + BM * 4 * 4)

// f16-accumulate legacy mma: D,C are 2 regs (half2 x2)
__device__ __forceinline__ void mma_f16acc(uint32_t c[2],
                                           uint32_t a0, uint32_t a1, uint32_t a2, uint32_t a3,
                                           uint32_t b0, uint32_t b1) {
    asm volatile(
        "mma.sync.aligned.m16n8k16.row.col.f16.f16.f16.f16 "
        "{%0,%1}, {%2,%3,%4,%5}, {%6,%7}, {%0,%1};\n"
        : "+r"(c[0]), "+r"(c[1])
        : "r"(a0), "r"(a1), "r"(a2), "r"(a3), "r"(b0), "r"(b1));
}
__device__ __forceinline__ void ldsm_x4(uint32_t addr, uint32_t& r0, uint32_t& r1,
                                        uint32_t& r2, uint32_t& r3) {
    asm volatile("ldmatrix.sync.aligned.m8n8.x4.shared.b16 {%0,%1,%2,%3}, [%4];"
                 : "=r"(r0), "=r"(r1), "=r"(r2), "=r"(r3) : "r"(addr));
}
__device__ __forceinline__ void cp16(uint32_t dst, const void* src) {
    asm volatile("cp.async.ca.shared.global [%0], [%1], 16;" :: "r"(dst), "l"(src) : "memory");
}

__global__ void __launch_bounds__(512, 1) k_gemm_e(const float* __restrict__ A,
                                                   const float* __restrict__ Wx,
                                                   const float* __restrict__ Wy,
                                                   const float* __restrict__ Wz,
                                                   const float* __restrict__ Wh,
                                                   const float* __restrict__ bs) {
    extern __shared__ __align__(128) char smem[];
    uint32_t sbase;
    asm("{ .reg .u64 t; cvta.to.shared.u64 t, %1; cvt.u32.u64 %0, t; }" : "=r"(sbase) : "l"(smem));

    const int tid  = threadIdx.x;
    const int lane = tid & 31, wid = tid >> 5;
    const int grp  = lane >> 2, tig = lane & 3;
    const int lbase = blockIdx.x * 16;

    const int mrow = tid >> 2;                    // local row = t*16 + (l-lbase)
    const int t_st = mrow >> 4;
    const int l_st = lbase + (mrow & 15);
    const float* Arow = A  + ((size_t)t_st * L_DIM + l_st) * D_DIM + (tid & 3) * 8;
    const float* wxp  = Wx + (size_t)l_st * D_DIM + (tid & 3) * 8;
    const float* wyp  = Wy + (size_t)l_st * D_DIM + (tid & 3) * 8;
    const float* wzp  = Wz + (size_t)l_st * D_DIM + (tid & 3) * 8;
    const uint32_t aDst = (uint32_t)(mrow * SAS + (tid & 3) * 8) * 2;
    const int bn = tid >> 1;
    const int bsg = (tid & 1) * 2;
    const __half* Bsrc = g_BT + (size_t)bn * D_DIM + bsg * 8;
    const uint32_t bDst = (uint32_t)(bn * SAS + bsg * 8) * 2;

    const int aRowL = lane & 15;
    const int aColL = (lane >> 4) << 3;
    const int bRowL = (lane & 7) + ((lane >> 4) << 3);
    const int bColL = ((lane >> 3) & 1) << 3;
    const uint32_t offA[2] = {sbase + OFF_A0, sbase + OFF_A1};
    const uint32_t offB[2] = {sbase + OFF_B0, sbase + OFF_B1};

    const int wm = (wid & 3) * 32;
    const int wn = (wid >> 2) * 64;

    uint32_t acc[2][8][2];
    #pragma unroll
    for (int i = 0; i < 2; i++)
        #pragma unroll
        for (int j = 0; j < 8; j++) { acc[i][j][0] = 0u; acc[i][j][1] = 0u; }

    float dx = 0.f, dy = 0.f, dz = 0.f;

    // ---- prologue: stage kt=0 ----
    float4 arc0 = *(const float4*)(Arow);
    float4 arc1 = *(const float4*)(Arow + 4);
    cp16(offB[0] + bDst,      Bsrc);
    cp16(offB[0] + bDst + 16, Bsrc + 8);
    asm volatile("cp.async.commit_group;" ::: "memory");
    {
        __half2 h01 = __float22half2_rn(make_float2(arc0.x, arc0.y));
        __half2 h23 = __float22half2_rn(make_float2(arc0.z, arc0.w));
        __half2 h45 = __float22half2_rn(make_float2(arc1.x, arc1.y));
        __half2 h67 = __float22half2_rn(make_float2(arc1.z, arc1.w));
        asm volatile("st.shared.v4.b32 [%0], {%1,%2,%3,%4};"
                     :: "r"(offA[0] + aDst), "r"(*(uint32_t*)&h01), "r"(*(uint32_t*)&h23),
                        "r"(*(uint32_t*)&h45), "r"(*(uint32_t*)&h67) : "memory");
    }
    asm volatile("cp.async.wait_group 0;" ::: "memory");
    __syncthreads();

    for (int kt = 0; kt < D_DIM / BK; kt++) {
        const int s = kt & 1;
        float4 arn0, arn1;
        // ---- issue next-stage copies FIRST (overlap with compute) ----
        if (kt + 1 < D_DIM / BK) {
            cp16(offB[s ^ 1] + bDst,      Bsrc + (kt + 1) * BK);
            cp16(offB[s ^ 1] + bDst + 16, Bsrc + (kt + 1) * BK + 8);
            asm volatile("cp.async.commit_group;" ::: "memory");
            arn0 = *(const float4*)(Arow + (kt + 1) * BK);
            arn1 = *(const float4*)(Arow + (kt + 1) * BK + 4);
        }
        // ---- dec dots on current A regs ----
        {
            const float4 x0 = *(const float4*)(wxp + kt * BK);
            const float4 x1 = *(const float4*)(wxp + kt * BK + 4);
            const float4 y0 = *(const float4*)(wyp + kt * BK);
            const float4 y1 = *(const float4*)(wyp + kt * BK + 4);
            const float4 z0 = *(const float4*)(wzp + kt * BK);
            const float4 z1 = *(const float4*)(wzp + kt * BK + 4);
            dx += arc0.x*x0.x + arc0.y*x0.y + arc0.z*x0.z + arc0.w*x0.w
                + arc1.x*x1.x + arc1.y*x1.y + arc1.z*x1.z + arc1.w*x1.w;
            dy += arc0.x*y0.x + arc0.y*y0.y + arc0.z*y0.z + arc0.w*y0.w
                + arc1.x*y1.x + arc1.y*y1.y + arc1.z*y1.z + arc1.w*y1.w;
            dz += arc0.x*z0.x + arc0.y*z0.y + arc0.z*z0.z + arc0.w*z0.w
                + arc1.x*z1.x + arc1.y*z1.y + arc1.z*z1.z + arc1.w*z1.w;
        }
        // ---- compute on stage s ----
        #pragma unroll
        for (int ks = 0; ks < 2; ks++) {
            uint32_t bf[8][2];
            #pragma unroll
            for (int p = 0; p < 4; p++) {
                uint32_t addr = offB[s] + 2u * ((wn + p * 16 + bRowL) * SAS + ks * 16 + bColL);
                ldsm_x4(addr, bf[2*p][0], bf[2*p][1], bf[2*p+1][0], bf[2*p+1][1]);
            }
            #pragma unroll
            for (int mi = 0; mi < 2; mi++) {
                uint32_t a0, a1, a2, a3;
                uint32_t addr = offA[s] + 2u * ((wm + mi * 16 + aRowL) * SAS + ks * 16 + aColL);
                ldsm_x4(addr, a0, a1, a2, a3);
                #pragma unroll
                for (int ni = 0; ni < 8; ni++)
                    mma_f16acc(acc[mi][ni], a0, a1, a2, a3, bf[ni][0], bf[ni][1]);
            }
        }
        // ---- stage next A, wait for next B ----
        if (kt + 1 < D_DIM / BK) {
            __half2 h01 = __float22half2_rn(make_float2(arn0.x, arn0.y));
            __half2 h23 = __float22half2_rn(make_float2(arn0.z, arn0.w));
            __half2 h45 = __float22half2_rn(make_float2(arn1.x, arn1.y));
            __half2 h67 = __float22half2_rn(make_float2(arn1.z, arn1.w));
            asm volatile("st.shared.v4.b32 [%0], {%1,%2,%3,%4};"
                         :: "r"(offA[s ^ 1] + aDst), "r"(*(uint32_t*)&h01), "r"(*(uint32_t*)&h23),
                            "r"(*(uint32_t*)&h45), "r"(*(uint32_t*)&h67) : "memory");
            asm volatile("cp.async.wait_group 0;" ::: "memory");
            arc0 = arn0; arc1 = arn1;
        }
        __syncthreads();
    }

    // ---- dots write-out (quad reduce) ----
    dx += __shfl_xor_sync(0xffffffffu, dx, 1); dx += __shfl_xor_sync(0xffffffffu, dx, 2);
    dy += __shfl_xor_sync(0xffffffffu, dy, 1); dy += __shfl_xor_sync(0xffffffffu, dy, 2);
    dz += __shfl_xor_sync(0xffffffffu, dz, 1); dz += __shfl_xor_sync(0xffffffffu, dz, 2);
    if ((tid & 3) == 0) {
        size_t rg = (size_t)t_st * L_DIM + l_st;
        g_dxyz[rg * 3 + 0] = dx;
        g_dxyz[rg * 3 + 1] = dy;
        g_dxyz[rg * 3 + 2] = dz;
    }

    // ---- epilogue: unpack f16 accs, store E + pa partials ----
    float* spa = (float*)(smem + OFF_SPA);        // [128][4]
    float pap[4] = {0.f, 0.f, 0.f, 0.f};
    const int t_w = (wm >> 4);
    #pragma unroll
    for (int mi = 0; mi < 2; mi++) {
        const int l0 = lbase + grp, l1 = lbase + grp + 8;
        const size_t rg0 = (size_t)(t_w + mi) * L_DIM + l0;
        const size_t rg1 = (size_t)(t_w + mi) * L_DIM + l1;
        const float* wh0 = Wh + (size_t)l0 * H_DIM;
        const float* wh1 = Wh + (size_t)l1 * H_DIM;
        #pragma unroll
        for (int ni = 0; ni < 8; ni++) {
            int col = wn + ni * 8 + 2 * tig;
            float2 lo = __half22float2(*(__half2*)&acc[mi][ni][0]);   // row rg0
            float2 hi = __half22float2(*(__half2*)&acc[mi][ni][1]);   // row rg1
            *(float2*)&g_E[rg0 * H_DIM + col] = lo;
            *(float2*)&g_E[rg1 * H_DIM + col] = hi;
            float2 bsv = *(const float2*)&bs[col];
            float2 w0  = *(const float2*)&wh0[col];
            float2 w1  = *(const float2*)&wh1[col];
            pap[mi*2]   += w0.x * tanhap(lo.x + bsv.x) + w0.y * tanhap(lo.y + bsv.y);
            pap[mi*2+1] += w1.x * tanhap(hi.x + bsv.x) + w1.y * tanhap(hi.y + bsv.y);
        }
    }
    #pragma unroll
    for (int j = 0; j < 4; j++) {
        pap[j] += __shfl_xor_sync(0xffffffffu, pap[j], 1);
        pap[j] += __shfl_xor_sync(0xffffffffu, pap[j], 2);
    }
    if (tig == 0) {
        #pragma unroll
        for (int mi = 0; mi < 2; mi++) {
            spa[(wm + mi * 16 + grp) * 4 + (wid >> 2)]     = pap[mi*2];
            spa[(wm + mi * 16 + grp + 8) * 4 + (wid >> 2)] = pap[mi*2+1];
        }
    }
    __syncthreads();
    if (tid < BM) {
        float s = (spa[tid*4] + spa[tid*4+1]) + (spa[tid*4+2] + spa[tid*4+3]);
        size_t rg = (size_t)(tid >> 4) * L_DIM + lbase + (tid & 15);
        g_pa[rg] = s;
    }
}

// ---------------- kernel 2: fused sequential recurrence ----------------
__global__ void __launch_bounds__(256) k_seq(const float* __restrict__ rois,
                                             const float* __restrict__ Wh,
                                             const float* __restrict__ bs,
                                             const float* __restrict__ bx,
                                             const float* __restrict__ by,
                                             const float* __restrict__ bz,
                                             float* __restrict__ out) {
    int wid = threadIdx.x >> 5, lane = threadIdx.x & 31;
    int l = blockIdx.x * 8 + wid;

    float wh[8], bsr[8], S[8];
    #pragma unroll
    for (int i = 0; i < 8; i++) {
        int j = i * 32 + lane;
        wh[i]  = Wh[(size_t)l * H_DIM + j];
        bsr[i] = bs[j];
        S[i]   = g_E[(size_t)l * H_DIM + j];
    }

    float e[7][8], dxs[7], dys[7], dzs[7], pas[7];
    #pragma unroll
    for (int t = 0; t < 7; t++) {
        size_t r = (size_t)(t + 1) * L_DIM + l;
        #pragma unroll
        for (int i = 0; i < 8; i++)
            e[t][i] = g_E[r * H_DIM + i * 32 + lane];
        dxs[t] = g_dxyz[r * 3 + 0];
        dys[t] = g_dxyz[r * 3 + 1];
        dzs[t] = g_dxyz[r * 3 + 2];
        pas[t] = g_pa[r];
    }

    float X = g_dxyz[(size_t)l * 3 + 0];
    float Y = g_dxyz[(size_t)l * 3 + 1];
    float Z = g_dxyz[(size_t)l * 3 + 2];
    float cx = rois[(size_t)l * 3 + 0];
    float cy = rois[(size_t)l * 3 + 1];
    float cz = rois[(size_t)l * 3 + 2];
    float bxl = bx[l], byl = by[l], bzl = bz[l];
    const float s0 = 1.0f / 767.0f, s2 = 1.0f / 575.0f;

    float px = (X + bxl) * s0 + cx;
    float py = (Y + byl) * s0 + cy;
    float pz = (Z + bzl) * s2 + cz;
    if (lane == 0) {
        out[(size_t)l * 3 + 0] = px;
        out[(size_t)l * 3 + 1] = py;
        out[(size_t)l * 3 + 2] = pz;
    }

    #pragma unroll
    for (int t = 0; t < 7; t++) {
        float q[8];
        #pragma unroll
        for (int i = 0; i < 8; i++)
            q[i] = wh[i] * tanhap(S[i] + bsr[i]);
        float pf = ((q[0]+q[1]) + (q[2]+q[3])) + ((q[4]+q[5]) + (q[6]+q[7]));
        #pragma unroll
        for (int o = 16; o > 0; o >>= 1)
            pf += __shfl_xor_sync(0xffffffffu, pf, o);

        float g0 = fmaf(0.5f, tanhap(0.5f * (pf - pas[t])), 0.5f);
        float g1 = 1.0f - g0;

        #pragma unroll
        for (int i = 0; i < 8; i++) S[i] = g0 * S[i] + g1 * e[t][i];

        X = g0 * X + g1 * dxs[t];
        Y = g0 * Y + g1 * dys[t];
        Z = g0 * Z + g1 * dzs[t];
        cx = g0 * cx + g1 * px;
        cy = g0 * cy + g1 * py;
        cz = g0 * cz + g1 * pz;
        px = (X + bxl) * s0 + cx;
        py = (Y + byl) * s0 + cy;
        pz = (Z + bzl) * s2 + cz;
        if (lane == 0) {
            size_t r = (size_t)(t + 1) * L_DIM + l;
            out[r * 3 + 0] = px;
            out[r * 3 + 1] = py;
            out[r * 3 + 2] = pz;
        }
    }
}

// ---------------- launch ----------------
extern "C" void kernel_launch(void* const* d_in, const int* in_sizes, int n_in,
                              void* d_out, int out_size) {
    const float* emb  = (const float*)d_in[0];
    const float* rois = (const float*)d_in[1];
    const float* Wx   = (const float*)d_in[2];
    const float* bx   = (const float*)d_in[3];
    const float* Wy   = (const float*)d_in[4];
    const float* by   = (const float*)d_in[5];
    const float* Wz   = (const float*)d_in[6];
    const float* bz   = (const float*)d_in[7];
    const float* Ws   = (const float*)d_in[8];
    const float* bs   = (const float*)d_in[9];
    const float* Wh   = (const float*)d_in[10];
    // d_in[11] = bh: cancels in the 2-way softmax.
    float* out = (float*)d_out;

    static int attr_set = 0;
    if (!attr_set) {
        cudaFuncSetAttribute(k_gemm_e, cudaFuncAttributeMaxDynamicSharedMemorySize, SMEM_TOTAL);
        attr_set = 1;
    }

    k_convert_ws<<<dim3(8, 16), dim3(32, 8)>>>(Ws);
    k_gemm_e<<<L_DIM / 16, 512, SMEM_TOTAL>>>(emb, Wx, Wy, Wz, Wh, bs);
    k_seq<<<L_DIM / 8, 256>>>(rois, Wh, bs, bx, by, bz, out);
}